// round 13
// baseline (speedup 1.0000x reference)
#include <cuda_runtime.h>
#include <cuda_bf16.h>
#include <math.h>
#include <stdint.h>

#define N_NODES 50000
#define N_EDGES 800000
#define D_IN    128
#define D_HID   128
#define D_OUT   256
#define SCAN_BLOCKS 196   // ceil(N_NODES/256)

// ---------------- scratch (static device globals — no allocations) ----------
__device__ __align__(16) float g_h[(size_t)N_NODES * D_HID];
__device__ __align__(16) float g_agg[(size_t)N_NODES * D_IN];
__device__ int   g_deg[N_NODES];
__device__ int   g_row[N_NODES + 1];
__device__ int   g_cursor[N_NODES];
__device__ int   g_csr[N_EDGES];
__device__ int   g_stmp[N_NODES];
__device__ int   g_bsum[SCAN_BLOCKS];
__device__ int   g_boff[SCAN_BLOCKS];

// weights pre-transposed to [N][K=128], bf16 split hi/lo
__device__ __align__(16) __nv_bfloat16 g_w1lh[128 * 128], g_w1ll[128 * 128];
__device__ __align__(16) __nv_bfloat16 g_w1rh[128 * 128], g_w1rl[128 * 128];
__device__ __align__(16) __nv_bfloat16 g_w2lh[256 * 128], g_w2ll[256 * 128];
__device__ __align__(16) __nv_bfloat16 g_w2rh[256 * 128], g_w2rl[256 * 128];

// ---------------- helpers ----------------
__device__ __forceinline__ uint32_t smem_u32(const void* p) {
    uint32_t a;
    asm("{ .reg .u64 t; cvta.to.shared.u64 t, %1; cvt.u32.u64 %0, t; }"
        : "=r"(a) : "l"(p));
    return a;
}
__device__ __forceinline__ void ldsm4(uint32_t* r, uint32_t addr) {
    asm volatile("ldmatrix.sync.aligned.m8n8.x4.shared.b16 {%0,%1,%2,%3}, [%4];"
                 : "=r"(r[0]), "=r"(r[1]), "=r"(r[2]), "=r"(r[3]) : "r"(addr));
}
__device__ __forceinline__ void mma16816(float* c, const uint32_t* a,
                                         uint32_t b0, uint32_t b1) {
    asm volatile("mma.sync.aligned.m16n8k16.row.col.f32.bf16.bf16.f32 "
                 "{%0,%1,%2,%3}, {%4,%5,%6,%7}, {%8,%9}, {%0,%1,%2,%3};"
                 : "+f"(c[0]), "+f"(c[1]), "+f"(c[2]), "+f"(c[3])
                 : "r"(a[0]), "r"(a[1]), "r"(a[2]), "r"(a[3]), "r"(b0), "r"(b1));
}
#define STS128(addr, a, b, c, d)                                                \
    asm volatile("st.shared.v4.b32 [%0], {%1, %2, %3, %4};"                     \
                 :: "r"(addr), "r"(a), "r"(b), "r"(c), "r"(d) : "memory")

__device__ __forceinline__ float sigf(float v) { return 1.f / (1.f + __expf(-v)); }

__device__ __forceinline__ int warp_incl_scan(int v, int lane) {
#pragma unroll
    for (int off = 1; off < 32; off <<= 1) {
        int n = __shfl_up_sync(0xffffffffu, v, off);
        if (lane >= off) v += n;
    }
    return v;
}

// ---------------- weight prep: fp32 [K,N] -> bf16 hi/lo [N,K] ---------------
__global__ void k_prep_w(const float* __restrict__ W1l, const float* __restrict__ W1r,
                         const float* __restrict__ W2l, const float* __restrict__ W2r) {
    int i = blockIdx.x * blockDim.x + threadIdx.x;
    const float* W; __nv_bfloat16* H; __nv_bfloat16* L; int N; int t;
    if (i < 16384)      { W = W1l; H = g_w1lh; L = g_w1ll; N = 128; t = i; }
    else if (i < 32768) { W = W1r; H = g_w1rh; L = g_w1rl; N = 128; t = i - 16384; }
    else if (i < 65536) { W = W2l; H = g_w2lh; L = g_w2ll; N = 256; t = i - 32768; }
    else if (i < 98304) { W = W2r; H = g_w2rh; L = g_w2rl; N = 256; t = i - 65536; }
    else return;
    int n = t >> 7, k = t & 127;
    float v = W[k * N + n];
    __nv_bfloat16 h = __float2bfloat16(v);
    H[t] = h;
    L[t] = __float2bfloat16(v - __bfloat162float(h));
}

// ---------------- CSR build ----------------
__global__ void k_zero_deg() {
    int i = blockIdx.x * blockDim.x + threadIdx.x;
    if (i < N_NODES) g_deg[i] = 0;
}
__global__ void k_count(const int* __restrict__ dst) {
    for (int e = blockIdx.x * blockDim.x + threadIdx.x; e < N_EDGES;
         e += gridDim.x * blockDim.x)
        atomicAdd(&g_deg[dst[e]], 1);
}

__global__ void k_scan1() {
    __shared__ int wsum[8];
    const int t = threadIdx.x;
    const int i = blockIdx.x * 256 + t;
    const int lane = t & 31, w = t >> 5;
    int d = (i < N_NODES) ? g_deg[i] : 0;
    int v = warp_incl_scan(d, lane);
    if (lane == 31) wsum[w] = v;
    __syncthreads();
    if (w == 0) {
        int s = (lane < 8) ? wsum[lane] : 0;
#pragma unroll
        for (int off = 1; off < 8; off <<= 1) {
            int n = __shfl_up_sync(0xffffffffu, s, off);
            if (lane >= off) s += n;
        }
        if (lane < 8) wsum[lane] = s;
    }
    __syncthreads();
    int incl = v + (w ? wsum[w - 1] : 0);
    if (i < N_NODES) g_stmp[i] = incl - d;
    if (t == 255) g_bsum[blockIdx.x] = incl;
}

__global__ void k_scan2() {
    __shared__ int wsum[8];
    const int t = threadIdx.x;
    const int lane = t & 31, w = t >> 5;
    int d = (t < SCAN_BLOCKS) ? g_bsum[t] : 0;
    int v = warp_incl_scan(d, lane);
    if (lane == 31) wsum[w] = v;
    __syncthreads();
    if (w == 0) {
        int s = (lane < 8) ? wsum[lane] : 0;
#pragma unroll
        for (int off = 1; off < 8; off <<= 1) {
            int n = __shfl_up_sync(0xffffffffu, s, off);
            if (lane >= off) s += n;
        }
        if (lane < 8) wsum[lane] = s;
    }
    __syncthreads();
    int incl = v + (w ? wsum[w - 1] : 0);
    if (t < SCAN_BLOCKS) g_boff[t] = incl - d;
}

__global__ void k_scan3() {
    const int i = blockIdx.x * 256 + threadIdx.x;
    if (i < N_NODES) {
        int r = g_stmp[i] + g_boff[i >> 8];
        g_row[i] = r;
        g_cursor[i] = r;
    }
    if (i == 0) g_row[N_NODES] = N_EDGES;
}

__global__ void k_fill(const int* __restrict__ src, const int* __restrict__ dst) {
    for (int e = blockIdx.x * blockDim.x + threadIdx.x; e < N_EDGES;
         e += gridDim.x * blockDim.x) {
        int d = dst[e];
        int p = atomicAdd(&g_cursor[d], 1);
        g_csr[p] = src[e];
    }
}

// ---------------- mean aggregation: one warp per destination node -----------
template <bool USE_H>
__global__ void __launch_bounds__(256) k_agg(const float* __restrict__ xin) {
    const float* __restrict__ feat = USE_H ? (const float*)g_h : xin;
    int warp = threadIdx.x >> 5;
    int lane = threadIdx.x & 31;
    int node = blockIdx.x * 8 + warp;
    if (node >= N_NODES) return;
    int s = g_row[node];
    int e = g_row[node + 1];

    float4 a0 = make_float4(0.f, 0.f, 0.f, 0.f);
    float4 a1 = make_float4(0.f, 0.f, 0.f, 0.f);
    float4 a2 = make_float4(0.f, 0.f, 0.f, 0.f);
    float4 a3 = make_float4(0.f, 0.f, 0.f, 0.f);
    int i = s;
    for (; i + 3 < e; i += 4) {
        int u0 = g_csr[i];
        int u1 = g_csr[i + 1];
        int u2 = g_csr[i + 2];
        int u3 = g_csr[i + 3];
        float4 v0 = *(const float4*)(feat + (size_t)u0 * 128 + lane * 4);
        float4 v1 = *(const float4*)(feat + (size_t)u1 * 128 + lane * 4);
        float4 v2 = *(const float4*)(feat + (size_t)u2 * 128 + lane * 4);
        float4 v3 = *(const float4*)(feat + (size_t)u3 * 128 + lane * 4);
        a0.x += v0.x; a0.y += v0.y; a0.z += v0.z; a0.w += v0.w;
        a1.x += v1.x; a1.y += v1.y; a1.z += v1.z; a1.w += v1.w;
        a2.x += v2.x; a2.y += v2.y; a2.z += v2.z; a2.w += v2.w;
        a3.x += v3.x; a3.y += v3.y; a3.z += v3.z; a3.w += v3.w;
    }
    for (; i < e; i++) {
        int u0 = g_csr[i];
        float4 v0 = *(const float4*)(feat + (size_t)u0 * 128 + lane * 4);
        a0.x += v0.x; a0.y += v0.y; a0.z += v0.z; a0.w += v0.w;
    }
    float invd = (e > s) ? 1.f / (float)(e - s) : 0.f;
    float4 r;
    r.x = (a0.x + a1.x + a2.x + a3.x) * invd;
    r.y = (a0.y + a1.y + a2.y + a3.y) * invd;
    r.z = (a0.z + a1.z + a2.z + a3.z) * invd;
    r.w = (a0.w + a1.w + a2.w + a3.w) * invd;
    *(float4*)(g_agg + (size_t)node * 128 + lane * 4) = r;
}

// ---------------- tensor-core GEMM (mma.sync bf16, 3-term split) ------------
// Block: 128 rows x N_OUT cols, 512 threads = 16 warps (4M x 4N).
// Warp tile: 32 x (N_OUT/4).  K chunked by 32 over (agg|self) x 4.
// smem: Ah/Al [128x32 bf16], Bh/Bl [N_OUT x 32 bf16], 16B-group XOR swizzle.
template <int LAYER>
__global__ void __launch_bounds__(512) k_mma(const float* __restrict__ xin,
                                             const float* __restrict__ bias,
                                             float* __restrict__ outp) {
    constexpr int N_OUT = (LAYER == 1) ? 128 : 256;
    constexpr int NFRAG = N_OUT / 32;
    constexpr int NX4   = NFRAG / 2;
    constexpr int WN    = N_OUT / 4;
    constexpr int OFF_AL = 8192;
    constexpr int OFF_BH = 16384;
    constexpr int BOFF   = N_OUT * 64;
    constexpr int OFF_RED = 16384 + 2 * BOFF;

    extern __shared__ __align__(16) char sm[];
    const uint32_t sb = smem_u32(sm);

    const int tid = threadIdx.x;
    const int wid = tid >> 5;
    const int lane = tid & 31;
    const int warpM = wid >> 2;                 // 0..3
    const int warpN = wid & 3;                  // 0..3
    const int m0 = blockIdx.x * 128;

    const float* A0 = g_agg;
    const float* A1 = (LAYER == 1) ? xin : (const float*)g_h;
    const __nv_bfloat16* B0h = (LAYER == 1) ? g_w1lh : g_w2lh;
    const __nv_bfloat16* B0l = (LAYER == 1) ? g_w1ll : g_w2ll;
    const __nv_bfloat16* B1h = (LAYER == 1) ? g_w1rh : g_w2rh;
    const __nv_bfloat16* B1l = (LAYER == 1) ? g_w1rl : g_w2rl;
    float* dst = (LAYER == 1) ? (float*)g_h : outp;

    float acc[2][NFRAG][4];
#pragma unroll
    for (int mi = 0; mi < 2; mi++)
#pragma unroll
        for (int nj = 0; nj < NFRAG; nj++)
#pragma unroll
            for (int c = 0; c < 4; c++) acc[mi][nj][c] = 0.f;

    uint32_t a_addr[2][2];
#pragma unroll
    for (int mi = 0; mi < 2; mi++) {
        int row = warpM * 32 + mi * 16 + (lane & 7) + ((lane >> 3) & 1) * 8;
#pragma unroll
        for (int k2 = 0; k2 < 2; k2++) {
            int kg = k2 * 2 + (lane >> 4);
            int gs = kg ^ ((row >> 1) & 3);
            a_addr[mi][k2] = sb + row * 64 + gs * 16;
        }
    }
    uint32_t b_addr[NX4][2];
#pragma unroll
    for (int q = 0; q < NX4; q++) {
        int n = warpN * WN + q * 16 + (lane & 7) + ((lane >> 4) & 1) * 8;
#pragma unroll
        for (int k2 = 0; k2 < 2; k2++) {
            int kg = k2 * 2 + ((lane >> 3) & 1);
            int gs = kg ^ ((n >> 1) & 3);
            b_addr[q][k2] = sb + OFF_BH + n * 64 + gs * 16;
        }
    }

#pragma unroll 1
    for (int chunk = 0; chunk < 8; chunk++) {
        const int srci = chunk >> 2;
        const int k0 = (chunk & 3) * 32;
        const float* Aptr = srci ? A1 : A0;
        const __nv_bfloat16* Bh = srci ? B1h : B0h;
        const __nv_bfloat16* Bl = srci ? B1l : B0l;

        // ---- A tile: fp32 -> bf16 hi/lo, swizzled (128 rows x 4 groups) ----
        {
            int r = tid >> 2, g = tid & 3;
            int gm = m0 + r;
            float v[8];
            if (gm < N_NODES) {
                const float* p = Aptr + (size_t)gm * 128 + k0 + g * 8;
                float4 p0 = *(const float4*)p;
                float4 p1 = *(const float4*)(p + 4);
                v[0] = p0.x; v[1] = p0.y; v[2] = p0.z; v[3] = p0.w;
                v[4] = p1.x; v[5] = p1.y; v[6] = p1.z; v[7] = p1.w;
            } else {
#pragma unroll
                for (int j = 0; j < 8; j++) v[j] = 0.f;
            }
            uint32_t hw[4], lw[4];
#pragma unroll
            for (int j = 0; j < 4; j++) {
                float a = v[2 * j], b = v[2 * j + 1];
                __nv_bfloat16 ah = __float2bfloat16(a);
                __nv_bfloat16 bh2 = __float2bfloat16(b);
                __nv_bfloat162 hp; hp.x = ah; hp.y = bh2;
                __nv_bfloat162 lp = __floats2bfloat162_rn(a - __bfloat162float(ah),
                                                          b - __bfloat162float(bh2));
                hw[j] = *(uint32_t*)&hp;
                lw[j] = *(uint32_t*)&lp;
            }
            int gs = g ^ ((r >> 1) & 3);
            uint32_t off = sb + r * 64 + gs * 16;
            STS128(off, hw[0], hw[1], hw[2], hw[3]);
            STS128(off + OFF_AL, lw[0], lw[1], lw[2], lw[3]);
        }
        // ---- B tile: prepped bf16 [N,128] -> swizzled smem ----
#pragma unroll
        for (int t = 0; t < N_OUT / 128; t++) {
            int idx = tid + t * 512;
            int r = idx >> 2, g = idx & 3;
            const char* ph = (const char*)Bh + r * 256 + k0 * 2 + g * 16;
            const char* pl = (const char*)Bl + r * 256 + k0 * 2 + g * 16;
            uint4 vh = *(const uint4*)ph;
            uint4 vl = *(const uint4*)pl;
            int gs = g ^ ((r >> 1) & 3);
            uint32_t off = sb + OFF_BH + r * 64 + gs * 16;
            STS128(off, vh.x, vh.y, vh.z, vh.w);
            STS128(off + BOFF, vl.x, vl.y, vl.z, vl.w);
        }
        __syncthreads();

#pragma unroll
        for (int k2 = 0; k2 < 2; k2++) {
            uint32_t ah[2][4], al[2][4];
            ldsm4(ah[0], a_addr[0][k2]);
            ldsm4(ah[1], a_addr[1][k2]);
            ldsm4(al[0], a_addr[0][k2] + OFF_AL);
            ldsm4(al[1], a_addr[1][k2] + OFF_AL);
#pragma unroll
            for (int q = 0; q < NX4; q++) {
                uint32_t bh[4], bl[4];
                ldsm4(bh, b_addr[q][k2]);
                ldsm4(bl, b_addr[q][k2] + BOFF);
#pragma unroll
                for (int s = 0; s < 2; s++) {
#pragma unroll
                    for (int mi = 0; mi < 2; mi++) {
                        float* c = acc[mi][2 * q + s];
                        mma16816(c, ah[mi], bh[2 * s], bh[2 * s + 1]);
                        mma16816(c, ah[mi], bl[2 * s], bl[2 * s + 1]);
                        mma16816(c, al[mi], bh[2 * s], bh[2 * s + 1]);
                    }
                }
            }
        }
        __syncthreads();
    }

    // ---- epilogue ----------------------------------------------------------
    const int quad = lane >> 4 ? 0 : 0;  // placeholder removed below
    const int qd = lane >> 2;
    const int qt = lane & 3;
    float* redq = (float*)(sm + OFF_RED);

#pragma unroll
    for (int mi = 0; mi < 2; mi++)
#pragma unroll
        for (int nj = 0; nj < NFRAG; nj++)
#pragma unroll
            for (int c = 0; c < 4; c++) {
                int col = warpN * WN + nj * 8 + qt * 2 + (c & 1);
                acc[mi][nj][c] = sigf(acc[mi][nj][c] + __ldg(bias + col));
            }

#pragma unroll
    for (int mi = 0; mi < 2; mi++)
#pragma unroll
        for (int half = 0; half < 2; half++) {
            float sq = 0.f;
#pragma unroll
            for (int nj = 0; nj < NFRAG; nj++) {
                float u0 = acc[mi][nj][half * 2], u1 = acc[mi][nj][half * 2 + 1];
                sq += u0 * u0 + u1 * u1;
            }
            sq += __shfl_xor_sync(0xffffffffu, sq, 1);
            sq += __shfl_xor_sync(0xffffffffu, sq, 2);
            int row = warpM * 32 + mi * 16 + qd + half * 8;
            if (qt == 0) redq[row * 4 + warpN] = sq;
        }
    __syncthreads();

    float inv[2][2];
#pragma unroll
    for (int mi = 0; mi < 2; mi++)
#pragma unroll
        for (int half = 0; half < 2; half++) {
            int row = warpM * 32 + mi * 16 + qd + half * 8;
            float t = redq[row * 4] + redq[row * 4 + 1] + redq[row * 4 + 2] +
                      redq[row * 4 + 3];
            inv[mi][half] = 1.f / fmaxf(sqrtf(t), 1e-12f);
        }

    if (LAYER == 1) {
#pragma unroll
        for (int mi = 0; mi < 2; mi++)
#pragma unroll
            for (int half = 0; half < 2; half++) {
                int row = warpM * 32 + mi * 16 + qd + half * 8;
                int gm = m0 + row;
                if (gm < N_NODES) {
#pragma unroll
                    for (int nj = 0; nj < NFRAG; nj++) {
                        float2 o;
                        o.x = acc[mi][nj][half * 2] * inv[mi][half];
                        o.y = acc[mi][nj][half * 2 + 1] * inv[mi][half];
                        *(float2*)(dst + (size_t)gm * N_OUT + warpN * WN + nj * 8 +
                                   qt * 2) = o;
                    }
                }
            }
    } else {
        float* redm = (float*)(sm + OFF_RED + 2048);
        float* reds = (float*)(sm + OFF_RED + 4096);
#pragma unroll
        for (int mi = 0; mi < 2; mi++)
#pragma unroll
            for (int half = 0; half < 2; half++) {
                float mx = -1e30f;
#pragma unroll
                for (int nj = 0; nj < NFRAG; nj++) {
                    float z0 = acc[mi][nj][half * 2] * inv[mi][half];
                    float z1 = acc[mi][nj][half * 2 + 1] * inv[mi][half];
                    acc[mi][nj][half * 2] = z0;
                    acc[mi][nj][half * 2 + 1] = z1;
                    mx = fmaxf(mx, fmaxf(z0, z1));
                }
                mx = fmaxf(mx, __shfl_xor_sync(0xffffffffu, mx, 1));
                mx = fmaxf(mx, __shfl_xor_sync(0xffffffffu, mx, 2));
                int row = warpM * 32 + mi * 16 + qd + half * 8;
                if (qt == 0) redm[row * 4 + warpN] = mx;
            }
        __syncthreads();
        float mxr[2][2];
#pragma unroll
        for (int mi = 0; mi < 2; mi++)
#pragma unroll
            for (int half = 0; half < 2; half++) {
                int row = warpM * 32 + mi * 16 + qd + half * 8;
                mxr[mi][half] = fmaxf(fmaxf(redm[row * 4], redm[row * 4 + 1]),
                                      fmaxf(redm[row * 4 + 2], redm[row * 4 + 3]));
            }
#pragma unroll
        for (int mi = 0; mi < 2; mi++)
#pragma unroll
            for (int half = 0; half < 2; half++) {
                float se = 0.f;
#pragma unroll
                for (int nj = 0; nj < NFRAG; nj++) {
                    se += __expf(acc[mi][nj][half * 2] - mxr[mi][half]);
                    se += __expf(acc[mi][nj][half * 2 + 1] - mxr[mi][half]);
                }
                se += __shfl_xor_sync(0xffffffffu, se, 1);
                se += __shfl_xor_sync(0xffffffffu, se, 2);
                int row = warpM * 32 + mi * 16 + qd + half * 8;
                if (qt == 0) reds[row * 4 + warpN] = se;
            }
        __syncthreads();
#pragma unroll
        for (int mi = 0; mi < 2; mi++)
#pragma unroll
            for (int half = 0; half < 2; half++) {
                int row = warpM * 32 + mi * 16 + qd + half * 8;
                float se = reds[row * 4] + reds[row * 4 + 1] + reds[row * 4 + 2] +
                           reds[row * 4 + 3];
                float lse = mxr[mi][half] + __logf(se);
                int gm = m0 + row;
                if (gm < N_NODES) {
#pragma unroll
                    for (int nj = 0; nj < NFRAG; nj++) {
                        float2 o;
                        o.x = acc[mi][nj][half * 2] - lse;
                        o.y = acc[mi][nj][half * 2 + 1] - lse;
                        *(float2*)(dst + (size_t)gm * N_OUT + warpN * WN + nj * 8 +
                                   qt * 2) = o;
                    }
                }
            }
    }
    (void)quad;
}

// ---------------- launch -----------------
#define SM_L1 (16384 + 2 * (128 * 64) + 2048)           // 34816
#define SM_L2 (16384 + 2 * (256 * 64) + 3 * 2048)       // 55296

extern "C" void kernel_launch(void* const* d_in, const int* in_sizes, int n_in,
                              void* d_out, int out_size) {
    const float* x   = (const float*)d_in[0];
    const int*   ei  = (const int*)d_in[1];
    const float* W1l = (const float*)d_in[2];
    const float* W1r = (const float*)d_in[3];
    const float* b1  = (const float*)d_in[4];
    const float* W2l = (const float*)d_in[5];
    const float* W2r = (const float*)d_in[6];
    const float* b2  = (const float*)d_in[7];
    float* out = (float*)d_out;

    const int* src = ei;            // edge_index[0]
    const int* dst = ei + N_EDGES;  // edge_index[1]

    cudaFuncSetAttribute(k_mma<1>, cudaFuncAttributeMaxDynamicSharedMemorySize, SM_L1);
    cudaFuncSetAttribute(k_mma<2>, cudaFuncAttributeMaxDynamicSharedMemorySize, SM_L2);

    // weight prep (bf16 split + transpose)
    k_prep_w<<<384, 256>>>(W1l, W1r, W2l, W2r);

    // CSR by destination (3-phase coalesced scan)
    k_zero_deg<<<SCAN_BLOCKS, 256>>>();
    k_count<<<592, 256>>>(dst);
    k_scan1<<<SCAN_BLOCKS, 256>>>();
    k_scan2<<<1, 256>>>();
    k_scan3<<<SCAN_BLOCKS, 256>>>();
    k_fill<<<592, 256>>>(src, dst);

    const int gblocks = (N_NODES + 127) / 128;   // 391

    // layer 1
    k_agg<false><<<(N_NODES + 7) / 8, 256>>>(x);
    k_mma<1><<<gblocks, 512, SM_L1>>>(x, b1, out);

    // layer 2
    k_agg<true><<<(N_NODES + 7) / 8, 256>>>(x);
    k_mma<2><<<gblocks, 512, SM_L2>>>(x, b2, out);
}

// round 14
// speedup vs baseline: 1.1583x; 1.1583x over previous
#include <cuda_runtime.h>
#include <cuda_bf16.h>
#include <math.h>
#include <stdint.h>

#define N_NODES 50000
#define N_EDGES 800000
#define D_IN    128
#define D_HID   128
#define D_OUT   256
#define SCAN_BLOCKS 196   // ceil(N_NODES/256)

// ---------------- scratch (static device globals — no allocations) ----------
__device__ __align__(16) float g_h[(size_t)N_NODES * D_HID];
__device__ __align__(16) float g_agg[(size_t)N_NODES * D_IN];
__device__ int   g_deg[N_NODES];
__device__ int   g_row[N_NODES + 1];
__device__ int   g_cursor[N_NODES];
__device__ int   g_csr[N_EDGES];
__device__ int   g_stmp[N_NODES];
__device__ int   g_bsum[SCAN_BLOCKS];
__device__ int   g_boff[SCAN_BLOCKS];

// weights pre-transposed to [N][K=128], bf16 split hi/lo
__device__ __align__(16) __nv_bfloat16 g_w1lh[128 * 128], g_w1ll[128 * 128];
__device__ __align__(16) __nv_bfloat16 g_w1rh[128 * 128], g_w1rl[128 * 128];
__device__ __align__(16) __nv_bfloat16 g_w2lh[256 * 128], g_w2ll[256 * 128];
__device__ __align__(16) __nv_bfloat16 g_w2rh[256 * 128], g_w2rl[256 * 128];

// ---------------- helpers ----------------
__device__ __forceinline__ uint32_t smem_u32(const void* p) {
    uint32_t a;
    asm("{ .reg .u64 t; cvta.to.shared.u64 t, %1; cvt.u32.u64 %0, t; }"
        : "=r"(a) : "l"(p));
    return a;
}
__device__ __forceinline__ void ldsm4(uint32_t* r, uint32_t addr) {
    asm volatile("ldmatrix.sync.aligned.m8n8.x4.shared.b16 {%0,%1,%2,%3}, [%4];"
                 : "=r"(r[0]), "=r"(r[1]), "=r"(r[2]), "=r"(r[3]) : "r"(addr));
}
__device__ __forceinline__ void mma16816(float* c, const uint32_t* a,
                                         uint32_t b0, uint32_t b1) {
    asm volatile("mma.sync.aligned.m16n8k16.row.col.f32.bf16.bf16.f32 "
                 "{%0,%1,%2,%3}, {%4,%5,%6,%7}, {%8,%9}, {%0,%1,%2,%3};"
                 : "+f"(c[0]), "+f"(c[1]), "+f"(c[2]), "+f"(c[3])
                 : "r"(a[0]), "r"(a[1]), "r"(a[2]), "r"(a[3]), "r"(b0), "r"(b1));
}
#define STS128(addr, a, b, c, d)                                                \
    asm volatile("st.shared.v4.b32 [%0], {%1, %2, %3, %4};"                     \
                 :: "r"(addr), "r"(a), "r"(b), "r"(c), "r"(d) : "memory")
#define CP_ASYNC16(smem, gptr)                                                  \
    asm volatile("cp.async.cg.shared.global [%0], [%1], 16;"                    \
                 :: "r"(smem), "l"(gptr) : "memory")
#define CP_COMMIT() asm volatile("cp.async.commit_group;" ::: "memory")
#define CP_WAIT(n)  asm volatile("cp.async.wait_group %0;" :: "n"(n) : "memory")

__device__ __forceinline__ float sigf(float v) { return 1.f / (1.f + __expf(-v)); }

__device__ __forceinline__ int warp_incl_scan(int v, int lane) {
#pragma unroll
    for (int off = 1; off < 32; off <<= 1) {
        int n = __shfl_up_sync(0xffffffffu, v, off);
        if (lane >= off) v += n;
    }
    return v;
}

// ---------------- weight prep: fp32 [K,N] -> bf16 hi/lo [N,K] ---------------
__global__ void k_prep_w(const float* __restrict__ W1l, const float* __restrict__ W1r,
                         const float* __restrict__ W2l, const float* __restrict__ W2r) {
    int i = blockIdx.x * blockDim.x + threadIdx.x;
    const float* W; __nv_bfloat16* H; __nv_bfloat16* L; int N; int t;
    if (i < 16384)      { W = W1l; H = g_w1lh; L = g_w1ll; N = 128; t = i; }
    else if (i < 32768) { W = W1r; H = g_w1rh; L = g_w1rl; N = 128; t = i - 16384; }
    else if (i < 65536) { W = W2l; H = g_w2lh; L = g_w2ll; N = 256; t = i - 32768; }
    else if (i < 98304) { W = W2r; H = g_w2rh; L = g_w2rl; N = 256; t = i - 65536; }
    else return;
    int n = t >> 7, k = t & 127;
    float v = W[k * N + n];
    __nv_bfloat16 h = __float2bfloat16(v);
    H[t] = h;
    L[t] = __float2bfloat16(v - __bfloat162float(h));
}

// ---------------- CSR build ----------------
__global__ void k_zero_deg() {
    int i = blockIdx.x * blockDim.x + threadIdx.x;
    if (i < N_NODES) g_deg[i] = 0;
}
__global__ void k_count(const int* __restrict__ dst) {
    for (int e = blockIdx.x * blockDim.x + threadIdx.x; e < N_EDGES;
         e += gridDim.x * blockDim.x)
        atomicAdd(&g_deg[dst[e]], 1);
}

__global__ void k_scan1() {
    __shared__ int wsum[8];
    const int t = threadIdx.x;
    const int i = blockIdx.x * 256 + t;
    const int lane = t & 31, w = t >> 5;
    int d = (i < N_NODES) ? g_deg[i] : 0;
    int v = warp_incl_scan(d, lane);
    if (lane == 31) wsum[w] = v;
    __syncthreads();
    if (w == 0) {
        int s = (lane < 8) ? wsum[lane] : 0;
#pragma unroll
        for (int off = 1; off < 8; off <<= 1) {
            int n = __shfl_up_sync(0xffffffffu, s, off);
            if (lane >= off) s += n;
        }
        if (lane < 8) wsum[lane] = s;
    }
    __syncthreads();
    int incl = v + (w ? wsum[w - 1] : 0);
    if (i < N_NODES) g_stmp[i] = incl - d;
    if (t == 255) g_bsum[blockIdx.x] = incl;
}

__global__ void k_scan2() {
    __shared__ int wsum[8];
    const int t = threadIdx.x;
    const int lane = t & 31, w = t >> 5;
    int d = (t < SCAN_BLOCKS) ? g_bsum[t] : 0;
    int v = warp_incl_scan(d, lane);
    if (lane == 31) wsum[w] = v;
    __syncthreads();
    if (w == 0) {
        int s = (lane < 8) ? wsum[lane] : 0;
#pragma unroll
        for (int off = 1; off < 8; off <<= 1) {
            int n = __shfl_up_sync(0xffffffffu, s, off);
            if (lane >= off) s += n;
        }
        if (lane < 8) wsum[lane] = s;
    }
    __syncthreads();
    int incl = v + (w ? wsum[w - 1] : 0);
    if (t < SCAN_BLOCKS) g_boff[t] = incl - d;
}

__global__ void k_scan3() {
    const int i = blockIdx.x * 256 + threadIdx.x;
    if (i < N_NODES) {
        int r = g_stmp[i] + g_boff[i >> 8];
        g_row[i] = r;
        g_cursor[i] = r;
    }
    if (i == 0) g_row[N_NODES] = N_EDGES;
}

__global__ void k_fill(const int* __restrict__ src, const int* __restrict__ dst) {
    for (int e = blockIdx.x * blockDim.x + threadIdx.x; e < N_EDGES;
         e += gridDim.x * blockDim.x) {
        int d = dst[e];
        int p = atomicAdd(&g_cursor[d], 1);
        g_csr[p] = src[e];
    }
}

// ---------------- mean aggregation: one warp per destination node -----------
template <bool USE_H>
__global__ void __launch_bounds__(256) k_agg(const float* __restrict__ xin) {
    const float* __restrict__ feat = USE_H ? (const float*)g_h : xin;
    int warp = threadIdx.x >> 5;
    int lane = threadIdx.x & 31;
    int node = blockIdx.x * 8 + warp;
    if (node >= N_NODES) return;
    int s = g_row[node];
    int e = g_row[node + 1];

    float4 a0 = make_float4(0.f, 0.f, 0.f, 0.f);
    float4 a1 = make_float4(0.f, 0.f, 0.f, 0.f);
    float4 a2 = make_float4(0.f, 0.f, 0.f, 0.f);
    float4 a3 = make_float4(0.f, 0.f, 0.f, 0.f);
    int i = s;
    for (; i + 3 < e; i += 4) {
        int u0 = g_csr[i];
        int u1 = g_csr[i + 1];
        int u2 = g_csr[i + 2];
        int u3 = g_csr[i + 3];
        float4 v0 = *(const float4*)(feat + (size_t)u0 * 128 + lane * 4);
        float4 v1 = *(const float4*)(feat + (size_t)u1 * 128 + lane * 4);
        float4 v2 = *(const float4*)(feat + (size_t)u2 * 128 + lane * 4);
        float4 v3 = *(const float4*)(feat + (size_t)u3 * 128 + lane * 4);
        a0.x += v0.x; a0.y += v0.y; a0.z += v0.z; a0.w += v0.w;
        a1.x += v1.x; a1.y += v1.y; a1.z += v1.z; a1.w += v1.w;
        a2.x += v2.x; a2.y += v2.y; a2.z += v2.z; a2.w += v2.w;
        a3.x += v3.x; a3.y += v3.y; a3.z += v3.z; a3.w += v3.w;
    }
    for (; i < e; i++) {
        int u0 = g_csr[i];
        float4 v0 = *(const float4*)(feat + (size_t)u0 * 128 + lane * 4);
        a0.x += v0.x; a0.y += v0.y; a0.z += v0.z; a0.w += v0.w;
    }
    float invd = (e > s) ? 1.f / (float)(e - s) : 0.f;
    float4 r;
    r.x = (a0.x + a1.x + a2.x + a3.x) * invd;
    r.y = (a0.y + a1.y + a2.y + a3.y) * invd;
    r.z = (a0.z + a1.z + a2.z + a3.z) * invd;
    r.w = (a0.w + a1.w + a2.w + a3.w) * invd;
    *(float4*)(g_agg + (size_t)node * 128 + lane * 4) = r;
}

// ---------------- tensor-core GEMM (mma.sync bf16, 3-term split) ------------
// Block: 64 rows x N_OUT cols, 256 threads = 8 warps (2M x 4N)  [R12 shape].
// Pipeline: B tiles double-buffered via cp.async; A prefetched in regs (L1).
// smem: A hi/lo [64x32 bf16] @ 0/4096; B hi/lo x2 bufs @ 8192; red @ OFF_RED.
template <int LAYER>
__global__ void __launch_bounds__(256, 2) k_mma(const float* __restrict__ xin,
                                                const float* __restrict__ bias,
                                                float* __restrict__ outp) {
    constexpr int N_OUT = (LAYER == 1) ? 128 : 256;
    constexpr int NFRAG = N_OUT / 32;
    constexpr int NX4   = NFRAG / 2;
    constexpr int WN    = N_OUT / 4;
    constexpr int OFF_AL = 4096;
    constexpr int OFF_B  = 8192;
    constexpr int BOFF   = N_OUT * 64;          // one B plane (hi or lo)
    constexpr int BUFS   = 2 * BOFF;            // hi+lo per buffer
    constexpr int OFF_RED = OFF_B + 2 * BUFS;
    constexpr bool PREF_A = (LAYER == 1);

    extern __shared__ __align__(16) char sm[];
    const uint32_t sb = smem_u32(sm);

    const int tid = threadIdx.x;
    const int wid = tid >> 5;
    const int lane = tid & 31;
    const int warpM = wid >> 2;                 // 0..1
    const int warpN = wid & 3;                  // 0..3
    const int m0 = blockIdx.x * 64;

    const float* A0 = g_agg;
    const float* A1 = (LAYER == 1) ? xin : (const float*)g_h;
    const __nv_bfloat16* B0h = (LAYER == 1) ? g_w1lh : g_w2lh;
    const __nv_bfloat16* B0l = (LAYER == 1) ? g_w1ll : g_w2ll;
    const __nv_bfloat16* B1h = (LAYER == 1) ? g_w1rh : g_w2rh;
    const __nv_bfloat16* B1l = (LAYER == 1) ? g_w1rl : g_w2rl;
    float* dst = (LAYER == 1) ? (float*)g_h : outp;

    float acc[2][NFRAG][4];
#pragma unroll
    for (int mi = 0; mi < 2; mi++)
#pragma unroll
        for (int nj = 0; nj < NFRAG; nj++)
#pragma unroll
            for (int c = 0; c < 4; c++) acc[mi][nj][c] = 0.f;

    uint32_t a_addr[2][2];
#pragma unroll
    for (int mi = 0; mi < 2; mi++) {
        int row = warpM * 32 + mi * 16 + (lane & 7) + ((lane >> 3) & 1) * 8;
#pragma unroll
        for (int k2 = 0; k2 < 2; k2++) {
            int kg = k2 * 2 + (lane >> 4);
            int gs = kg ^ ((row >> 1) & 3);
            a_addr[mi][k2] = sb + row * 64 + gs * 16;
        }
    }
    uint32_t b_addr[NX4][2];
#pragma unroll
    for (int q = 0; q < NX4; q++) {
        int n = warpN * WN + q * 16 + (lane & 7) + ((lane >> 4) & 1) * 8;
#pragma unroll
        for (int k2 = 0; k2 < 2; k2++) {
            int kg = k2 * 2 + ((lane >> 3) & 1);
            int gs = kg ^ ((n >> 1) & 3);
            b_addr[q][k2] = sb + OFF_B + n * 64 + gs * 16;
        }
    }

    // ---- pipeline helpers ----
    const int ar = tid >> 2, ag = tid & 3;
    const int ags = ag ^ ((ar >> 1) & 3);
    const uint32_t a_sts = sb + ar * 64 + ags * 16;

    auto loadA = [&](int c, float* v) {
        const int srci = c >> 2;
        const int k0 = (c & 3) * 32;
        const float* Aptr = srci ? A1 : A0;
        int gm = m0 + ar;
        if (gm < N_NODES) {
            const float* p = Aptr + (size_t)gm * 128 + k0 + ag * 8;
            float4 p0 = *(const float4*)p;
            float4 p1 = *(const float4*)(p + 4);
            v[0] = p0.x; v[1] = p0.y; v[2] = p0.z; v[3] = p0.w;
            v[4] = p1.x; v[5] = p1.y; v[6] = p1.z; v[7] = p1.w;
        } else {
#pragma unroll
            for (int j = 0; j < 8; j++) v[j] = 0.f;
        }
    };
    auto stsA = [&](const float* v) {
        uint32_t hw[4], lw[4];
#pragma unroll
        for (int j = 0; j < 4; j++) {
            float a = v[2 * j], b = v[2 * j + 1];
            __nv_bfloat16 ah = __float2bfloat16(a);
            __nv_bfloat16 bh2 = __float2bfloat16(b);
            __nv_bfloat162 hp; hp.x = ah; hp.y = bh2;
            __nv_bfloat162 lp = __floats2bfloat162_rn(a - __bfloat162float(ah),
                                                      b - __bfloat162float(bh2));
            hw[j] = *(uint32_t*)&hp;
            lw[j] = *(uint32_t*)&lp;
        }
        STS128(a_sts, hw[0], hw[1], hw[2], hw[3]);
        STS128(a_sts + OFF_AL, lw[0], lw[1], lw[2], lw[3]);
    };
    auto issueB = [&](int c) {
        const int srci = c >> 2;
        const int k0 = (c & 3) * 32;
        const __nv_bfloat16* Bh = srci ? B1h : B0h;
        const __nv_bfloat16* Bl = srci ? B1l : B0l;
        const uint32_t bufo = OFF_B + (uint32_t)(c & 1) * BUFS;
#pragma unroll
        for (int t = 0; t < N_OUT / 64; t++) {
            int idx = tid + t * 256;
            int r = idx >> 2, g = idx & 3;
            int gs = g ^ ((r >> 1) & 3);
            uint32_t off = sb + bufo + r * 64 + gs * 16;
            CP_ASYNC16(off, (const char*)Bh + r * 256 + k0 * 2 + g * 16);
            CP_ASYNC16(off + BOFF, (const char*)Bl + r * 256 + k0 * 2 + g * 16);
        }
        CP_COMMIT();
    };

    float av[8];
    issueB(0);
    if (PREF_A) loadA(0, av);

#pragma unroll 1
    for (int c = 0; c < 8; c++) {
        if (!PREF_A) loadA(c, av);
        stsA(av);
        if (c < 7) {
            issueB(c + 1);
            CP_WAIT(1);
        } else {
            CP_WAIT(0);
        }
        __syncthreads();
        if (PREF_A && c < 7) loadA(c + 1, av);

        const uint32_t bsel = (uint32_t)(c & 1) * BUFS;
#pragma unroll
        for (int k2 = 0; k2 < 2; k2++) {
            uint32_t ah[2][4], al[2][4];
            ldsm4(ah[0], a_addr[0][k2]);
            ldsm4(ah[1], a_addr[1][k2]);
            ldsm4(al[0], a_addr[0][k2] + OFF_AL);
            ldsm4(al[1], a_addr[1][k2] + OFF_AL);
#pragma unroll
            for (int q = 0; q < NX4; q++) {
                uint32_t bh[4], bl[4];
                ldsm4(bh, b_addr[q][k2] + bsel);
                ldsm4(bl, b_addr[q][k2] + bsel + BOFF);
#pragma unroll
                for (int s = 0; s < 2; s++) {
#pragma unroll
                    for (int mi = 0; mi < 2; mi++) {
                        float* cc = acc[mi][2 * q + s];
                        mma16816(cc, ah[mi], bh[2 * s], bh[2 * s + 1]);
                        mma16816(cc, ah[mi], bl[2 * s], bl[2 * s + 1]);
                        mma16816(cc, al[mi], bh[2 * s], bh[2 * s + 1]);
                    }
                }
            }
        }
        __syncthreads();
    }

    // ---- epilogue ----------------------------------------------------------
    const int qd = lane >> 2;
    const int qt = lane & 3;
    float* redq = (float*)(sm + OFF_RED);

#pragma unroll
    for (int mi = 0; mi < 2; mi++)
#pragma unroll
        for (int nj = 0; nj < NFRAG; nj++)
#pragma unroll
            for (int c = 0; c < 4; c++) {
                int col = warpN * WN + nj * 8 + qt * 2 + (c & 1);
                acc[mi][nj][c] = sigf(acc[mi][nj][c] + __ldg(bias + col));
            }

#pragma unroll
    for (int mi = 0; mi < 2; mi++)
#pragma unroll
        for (int half = 0; half < 2; half++) {
            float sq = 0.f;
#pragma unroll
            for (int nj = 0; nj < NFRAG; nj++) {
                float u0 = acc[mi][nj][half * 2], u1 = acc[mi][nj][half * 2 + 1];
                sq += u0 * u0 + u1 * u1;
            }
            sq += __shfl_xor_sync(0xffffffffu, sq, 1);
            sq += __shfl_xor_sync(0xffffffffu, sq, 2);
            int row = warpM * 32 + mi * 16 + qd + half * 8;
            if (qt == 0) redq[row * 4 + warpN] = sq;
        }
    __syncthreads();

    float inv[2][2];
#pragma unroll
    for (int mi = 0; mi < 2; mi++)
#pragma unroll
        for (int half = 0; half < 2; half++) {
            int row = warpM * 32 + mi * 16 + qd + half * 8;
            float t = redq[row * 4] + redq[row * 4 + 1] + redq[row * 4 + 2] +
                      redq[row * 4 + 3];
            inv[mi][half] = 1.f / fmaxf(sqrtf(t), 1e-12f);
        }

    if (LAYER == 1) {
#pragma unroll
        for (int mi = 0; mi < 2; mi++)
#pragma unroll
            for (int half = 0; half < 2; half++) {
                int row = warpM * 32 + mi * 16 + qd + half * 8;
                int gm = m0 + row;
                if (gm < N_NODES) {
#pragma unroll
                    for (int nj = 0; nj < NFRAG; nj++) {
                        float2 o;
                        o.x = acc[mi][nj][half * 2] * inv[mi][half];
                        o.y = acc[mi][nj][half * 2 + 1] * inv[mi][half];
                        *(float2*)(dst + (size_t)gm * N_OUT + warpN * WN + nj * 8 +
                                   qt * 2) = o;
                    }
                }
            }
    } else {
        float* redm = (float*)(sm + OFF_RED + 1024);
        float* reds = (float*)(sm + OFF_RED + 2048);
#pragma unroll
        for (int mi = 0; mi < 2; mi++)
#pragma unroll
            for (int half = 0; half < 2; half++) {
                float mx = -1e30f;
#pragma unroll
                for (int nj = 0; nj < NFRAG; nj++) {
                    float z0 = acc[mi][nj][half * 2] * inv[mi][half];
                    float z1 = acc[mi][nj][half * 2 + 1] * inv[mi][half];
                    acc[mi][nj][half * 2] = z0;
                    acc[mi][nj][half * 2 + 1] = z1;
                    mx = fmaxf(mx, fmaxf(z0, z1));
                }
                mx = fmaxf(mx, __shfl_xor_sync(0xffffffffu, mx, 1));
                mx = fmaxf(mx, __shfl_xor_sync(0xffffffffu, mx, 2));
                int row = warpM * 32 + mi * 16 + qd + half * 8;
                if (qt == 0) redm[row * 4 + warpN] = mx;
            }
        __syncthreads();
        float mxr[2][2];
#pragma unroll
        for (int mi = 0; mi < 2; mi++)
#pragma unroll
            for (int half = 0; half < 2; half++) {
                int row = warpM * 32 + mi * 16 + qd + half * 8;
                mxr[mi][half] = fmaxf(fmaxf(redm[row * 4], redm[row * 4 + 1]),
                                      fmaxf(redm[row * 4 + 2], redm[row * 4 + 3]));
            }
#pragma unroll
        for (int mi = 0; mi < 2; mi++)
#pragma unroll
            for (int half = 0; half < 2; half++) {
                float se = 0.f;
#pragma unroll
                for (int nj = 0; nj < NFRAG; nj++) {
                    se += __expf(acc[mi][nj][half * 2] - mxr[mi][half]);
                    se += __expf(acc[mi][nj][half * 2 + 1] - mxr[mi][half]);
                }
                se += __shfl_xor_sync(0xffffffffu, se, 1);
                se += __shfl_xor_sync(0xffffffffu, se, 2);
                int row = warpM * 32 + mi * 16 + qd + half * 8;
                if (qt == 0) reds[row * 4 + warpN] = se;
            }
        __syncthreads();
#pragma unroll
        for (int mi = 0; mi < 2; mi++)
#pragma unroll
            for (int half = 0; half < 2; half++) {
                int row = warpM * 32 + mi * 16 + qd + half * 8;
                float se = reds[row * 4] + reds[row * 4 + 1] + reds[row * 4 + 2] +
                           reds[row * 4 + 3];
                float lse = mxr[mi][half] + __logf(se);
                int gm = m0 + row;
                if (gm < N_NODES) {
#pragma unroll
                    for (int nj = 0; nj < NFRAG; nj++) {
                        float2 o;
                        o.x = acc[mi][nj][half * 2] - lse;
                        o.y = acc[mi][nj][half * 2 + 1] - lse;
                        *(float2*)(dst + (size_t)gm * N_OUT + warpN * WN + nj * 8 +
                                   qt * 2) = o;
                    }
                }
            }
    }
}

// ---------------- launch -----------------
// smem: A 8KB + B 2 bufs * 2 planes * (N_OUT*64) + reduction scratch
#define SM_L1 (8192 + 4 * (128 * 64) + 1024)    // 41984
#define SM_L2 (8192 + 4 * (256 * 64) + 3072)    // 76800

extern "C" void kernel_launch(void* const* d_in, const int* in_sizes, int n_in,
                              void* d_out, int out_size) {
    const float* x   = (const float*)d_in[0];
    const int*   ei  = (const int*)d_in[1];
    const float* W1l = (const float*)d_in[2];
    const float* W1r = (const float*)d_in[3];
    const float* b1  = (const float*)d_in[4];
    const float* W2l = (const float*)d_in[5];
    const float* W2r = (const float*)d_in[6];
    const float* b2  = (const float*)d_in[7];
    float* out = (float*)d_out;

    const int* src = ei;            // edge_index[0]
    const int* dst = ei + N_EDGES;  // edge_index[1]

    cudaFuncSetAttribute(k_mma<1>, cudaFuncAttributeMaxDynamicSharedMemorySize, SM_L1);
    cudaFuncSetAttribute(k_mma<2>, cudaFuncAttributeMaxDynamicSharedMemorySize, SM_L2);

    // weight prep (bf16 split + transpose)
    k_prep_w<<<384, 256>>>(W1l, W1r, W2l, W2r);

    // CSR by destination (3-phase coalesced scan)
    k_zero_deg<<<SCAN_BLOCKS, 256>>>();
    k_count<<<592, 256>>>(dst);
    k_scan1<<<SCAN_BLOCKS, 256>>>();
    k_scan2<<<1, 256>>>();
    k_scan3<<<SCAN_BLOCKS, 256>>>();
    k_fill<<<592, 256>>>(src, dst);

    const int gblocks = (N_NODES + 63) / 64;   // 782

    // layer 1
    k_agg<false><<<(N_NODES + 7) / 8, 256>>>(x);
    k_mma<1><<<gblocks, 256, SM_L1>>>(x, b1, out);

    // layer 2
    k_agg<true><<<(N_NODES + 7) / 8, 256>>>(x);
    k_mma<2><<<gblocks, 256, SM_L2>>>(x, b2, out);
}